// round 16
// baseline (speedup 1.0000x reference)
#include <cuda_runtime.h>

// Problem constants (fixed for this problem instance)
#define S_    2048
#define D_    512
#define H_    512
#define H3_   1536
#define KW_   3
#define MAXA_ 16     // max gather rows per step supported in metadata

#define GBLK 128     // persistent CTAs in scan kernel (all co-resident, 1/SM)
#define NW   4       // warps per CTA; GBLK*NW == H_ (one warp per output j)
#define NT   (NW * 32)
#define BAR1_TARGET (GBLK * NW)   // per-warp arrivals on bar1 (512)

// ---------------- device scratch (static: no runtime allocation) ----------------
__device__ float g_WI [S_ * H3_];
__device__ float g_AWI[S_ * H_];
__device__ float g_WWI[(size_t)S_ * KW_ * H3_];
__device__ float g_WhhT [H3_ * D_];
__device__ float g_aWhhT[H_  * H_];
__device__ float g_WwhhT[H3_ * H_];
__device__ float g_cbuf[(size_t)S_ * KW_ * H_];
__device__ unsigned g_bar[2 * S_];
__device__ int g_meta[S_];                 // nact | nsafe<<8 (rows gathered AT step t)
__device__ int g_rows[S_ * MAXA_];         // row index = pos*KW + slot (safe first)

// ---------------- fast transcendentals (ex2.approx-based; ~1e-6 rel err) ----------------
__device__ __forceinline__ float fexp(float x)
{
    float y;
    asm("ex2.approx.ftz.f32 %0, %1;" : "=f"(y) : "f"(x * 1.4426950408889634f));
    return y;
}
__device__ __forceinline__ float fsig(float x)
{
    return __fdividef(1.f, 1.f + fexp(-x));
}
__device__ __forceinline__ float ftanh(float x)
{
    float e = fexp(-2.f * x);
    return fmaf(2.f, __fdividef(1.f, 1.f + e), -1.f);
}

// ---------------- SGEMM body: C[M,N] = A[M,K] @ B[K,N] + bias ----------------
__device__ __forceinline__ void sgemm_body(
    const float* __restrict__ A, const float* __restrict__ B,
    const float* __restrict__ bias, float* __restrict__ C,
    int M, int N, int K, const int* __restrict__ rowIdx,
    int bx, int by, float As[8][128], float Bs[8][128])
{
    const int tid = threadIdx.x;
    const int tr = tid >> 4;
    const int tc = tid & 15;
    const int arow = tid >> 1;
    const int acol = (tid & 1) * 4;
    const int brow = tid >> 5;
    const int bcol = (tid & 31) * 4;

    const float* Abase;
    {
        int gr = by * 128 + arow;
        size_t r = rowIdx ? (size_t)rowIdx[gr] : (size_t)gr;
        Abase = A + r * (size_t)K + acol;
    }
    const float* Bbase = B + (size_t)brow * N + bx * 128 + bcol;

    float acc[8][8];
#pragma unroll
    for (int i = 0; i < 8; i++)
#pragma unroll
        for (int j = 0; j < 8; j++) acc[i][j] = 0.f;

    for (int k0 = 0; k0 < K; k0 += 8) {
        float4 av = *(const float4*)(Abase + k0);
        As[acol + 0][arow] = av.x;
        As[acol + 1][arow] = av.y;
        As[acol + 2][arow] = av.z;
        As[acol + 3][arow] = av.w;
        float4 bv = *(const float4*)(Bbase + (size_t)k0 * N);
        *(float4*)&Bs[brow][bcol] = bv;
        __syncthreads();
#pragma unroll
        for (int kk = 0; kk < 8; kk++) {
            float ar[8], br[8];
            float4 a0 = *(const float4*)&As[kk][tr * 8];
            float4 a1 = *(const float4*)&As[kk][tr * 8 + 4];
            ar[0] = a0.x; ar[1] = a0.y; ar[2] = a0.z; ar[3] = a0.w;
            ar[4] = a1.x; ar[5] = a1.y; ar[6] = a1.z; ar[7] = a1.w;
            float4 b0 = *(const float4*)&Bs[kk][tc * 8];
            float4 b1 = *(const float4*)&Bs[kk][tc * 8 + 4];
            br[0] = b0.x; br[1] = b0.y; br[2] = b0.z; br[3] = b0.w;
            br[4] = b1.x; br[5] = b1.y; br[6] = b1.z; br[7] = b1.w;
#pragma unroll
            for (int i = 0; i < 8; i++)
#pragma unroll
                for (int j = 0; j < 8; j++)
                    acc[i][j] = fmaf(ar[i], br[j], acc[i][j]);
        }
        __syncthreads();
    }

#pragma unroll
    for (int i = 0; i < 8; i++) {
        int row = by * 128 + tr * 8 + i;
#pragma unroll
        for (int j = 0; j < 8; j++) {
            int col = bx * 128 + tc * 8 + j;
            float v = acc[i][j];
            if (bias) v += bias[col];
            C[(size_t)row * N + col] = v;
        }
    }
}

// ---------------- launch 1: transposes + barrier clear + act-list metadata ----------------
__global__ void prep_fused(const float* __restrict__ w_hh,
                           const float* __restrict__ aw_hh,
                           const float* __restrict__ ww_hh,
                           const int* __restrict__ gpos,
                           const int* __restrict__ gslot,
                           const int* __restrict__ gmask, int Km)
{
    if (blockIdx.z < 3) {
        __shared__ float tile[32][33];
        const float* in; float* out; int R, C;
        if (blockIdx.z == 0)      { in = w_hh;  out = g_WhhT;  R = D_; C = H3_; }
        else if (blockIdx.z == 1) { in = aw_hh; out = g_aWhhT; R = H_; C = H_;  }
        else                      { in = ww_hh; out = g_WwhhT; R = H_; C = H3_; }

        int cx = blockIdx.x * 32, ry = blockIdx.y * 32;
        if (cx >= C || ry >= R) return;
        int x = cx + threadIdx.x;
#pragma unroll
        for (int i = 0; i < 32; i += 8) {
            int y = ry + threadIdx.y + i;
            tile[threadIdx.y + i][threadIdx.x] = in[(size_t)y * C + x];
        }
        __syncthreads();
        int x2 = ry + threadIdx.x;
#pragma unroll
        for (int i = 0; i < 32; i += 8) {
            int y2 = cx + threadIdx.y + i;
            out[(size_t)y2 * R + x2] = tile[threadIdx.x][threadIdx.y + i];
        }
        return;
    }

    // z == 3: clear barrier counters + build act-list metadata (one thread per t)
    int flat = blockIdx.y * gridDim.x + blockIdx.x;
    int g = flat * 256 + threadIdx.y * 32 + threadIdx.x;
    if (g < 2 * S_) g_bar[g] = 0;
    if (g < S_) {
        const int t = g;
        const int* gm = gmask + (size_t)t * Km;
        const int* gp = gpos  + (size_t)t * Km;
        const int* gs = gslot + (size_t)t * Km;
        int n = 0;
        for (int k = 0; k < Km && n < MAXA_; k++)      // safe rows first (pos < t-1)
            if (gm[k] && gp[k] != t - 1)
                g_rows[t * MAXA_ + n++] = gp[k] * KW_ + gs[k];
        int nsafe = n;
        for (int k = 0; k < Km && n < MAXA_; k++)      // fresh rows last (pos == t-1)
            if (gm[k] && gp[k] == t - 1)
                g_rows[t * MAXA_ + n++] = gp[k] * KW_ + gs[k];
        g_meta[t] = n | (nsafe << 8);
    }
}

// ---------------- launch 2: fused WI + AWI GEMMs ----------------
__global__ void __launch_bounds__(256) gemm_fused(
    const float* __restrict__ x,
    const float* __restrict__ W_ih, const float* __restrict__ b,
    const float* __restrict__ aW_ih, const float* __restrict__ ab)
{
    __shared__ float As[8][128];
    __shared__ float Bs[8][128];
    const int z = blockIdx.z;
    if (z == 1 && blockIdx.x >= H_ / 128) return;
    const float* B    = z ? aW_ih : W_ih;
    const float* bias = z ? ab    : b;
    float* C          = z ? g_AWI : g_WI;
    int N             = z ? H_    : H3_;
    sgemm_body(x, B, bias, C, S_, N, D_, nullptr, blockIdx.x, blockIdx.y, As, Bs);
}

// ---------------- launch 3: WWI GEMM (embedding-gathered A) ----------------
__global__ void __launch_bounds__(256) gemm_wwi(
    const float* __restrict__ word_emb, const float* __restrict__ Ww_ih,
    const float* __restrict__ bw, const int* __restrict__ word_ids)
{
    __shared__ float As[8][128];
    __shared__ float Bs[8][128];
    sgemm_body(word_emb, Ww_ih, bw, g_WWI, S_ * KW_, H3_, D_, word_ids,
               blockIdx.x, blockIdx.y, As, Bs);
}

// ---------------- scan helpers ----------------
__device__ __forceinline__ void load_row16(const float* base, int lane, float* r)
{
    const float4* p = (const float4*)base;
#pragma unroll
    for (int i = 0; i < 4; i++) {
        float4 v = p[lane + 32 * i];
        r[4 * i + 0] = v.x; r[4 * i + 1] = v.y;
        r[4 * i + 2] = v.z; r[4 * i + 3] = v.w;
    }
}

// per-warp arrival: lane 0 releases after ITS OWN prior stores (h1[j]).
__device__ __forceinline__ void bar1_arrive_warp(unsigned* ctr, int lane)
{
    if (lane == 0)
        asm volatile("red.release.gpu.global.add.u32 [%0], 1;" :: "l"(ctr) : "memory");
}

// CTA-level arrive (multi-lane stores need the syncthreads ordering)
__device__ __forceinline__ void bar_arrive_cta(unsigned* ctr)
{
    __syncthreads();
    if (threadIdx.x == 0)
        asm volatile("red.release.gpu.global.add.u32 [%0], 1;" :: "l"(ctr) : "memory");
}

__device__ __forceinline__ void bar_wait_warp(unsigned* ctr, unsigned target)
{
    unsigned v;
    do {
        asm volatile("ld.acquire.gpu.global.u32 %0, [%1];" : "=r"(v) : "l"(ctr) : "memory");
    } while (v < target);
}

// ---------------- persistent sequential scan (h-first, per-warp bar1) ----------------
__global__ void __launch_bounds__(NT, 1) scan_kernel(
    float* __restrict__ out_h, float* __restrict__ out_c)
{
    extern __shared__ float sm[];
    float* h_sh   = sm;            // H_ floats
    float* cin_sh = sm + H_;       // MAXA_ * H_ floats

    const int tid  = threadIdx.x;
    const int lane = tid & 31;
    const int wid  = tid >> 5;
    const int j    = blockIdx.x * NW + wid;              // 0..511

    // register-resident weight rows (columns of the original matrices)
    float wI[16], wO[16], wG[16], wA[16], wF[16], wIw[16], wGw[16];
    load_row16(g_WhhT  + (size_t)(0    + j) * D_, lane, wI);
    load_row16(g_WhhT  + (size_t)(H_   + j) * D_, lane, wO);
    load_row16(g_WhhT  + (size_t)(2*H_ + j) * D_, lane, wG);
    load_row16(g_aWhhT + (size_t)j * H_,          lane, wA);
    load_row16(g_WwhhT + (size_t)(0    + j) * H_, lane, wF);
    load_row16(g_WwhhT + (size_t)(H_   + j) * H_, lane, wIw);
    load_row16(g_WwhhT + (size_t)(2*H_ + j) * H_, lane, wGw);

    // ---- prologue: step 0 (h = 0; no words end at t=0 since len >= 2) ----
    float cx, h1;
    {
        float gi = fsig(g_WI[j]);
        float go = fsig(g_WI[H_ + j]);
        float gg = ftanh(g_WI[2 * H_ + j]);
        cx = gi * gg;                      // (1-i)*0 + i*g
        h1 = go * ftanh(cx);
        if (lane == 0) { out_h[j] = h1; out_c[j] = cx; }
    }
    bar1_arrive_warp(&g_bar[0], lane);     // per-warp: h(0)[j] released

    // shadow: WWI gates for word cells of t=0; meta/scalars for t+1 = 1
    float wwf = 0.f, wwq = 0.f, wwg = 0.f;
    if (lane < KW_) {
        const float* wr = g_WWI + (size_t)lane * H3_ + j;
        wwf = wr[0]; wwq = wr[H_]; wwg = wr[2 * H_];
    }
    int   meta_n = g_meta[1];
    float wi_t  = g_WI[(size_t)H3_ + j];
    float wo_t  = g_WI[(size_t)H3_ + H_ + j];
    float wg_t  = g_WI[(size_t)H3_ + 2 * H_ + j];
    float awi_t = g_AWI[(size_t)H_ + j];

    for (int t = 0; t < S_ - 1; t++) {
        __syncthreads();                   // seal shared buffers from prev iteration
        bar_wait_warp(&g_bar[2 * t], BAR1_TARGET);        // all 512 h(t)[j] visible

        const int nact = meta_n & 0xff;
        const int ns   = (meta_n >> 8) & 0xff;
        const bool need2 = nact > ns;                     // grid-uniform

        // coop stage: h(t) row + safe cin rows for t+1
        {
            ((float4*)h_sh)[tid] = ((const float4*)(out_h + (size_t)t * H_))[tid];
            for (int a = 0; a < ns; a++) {
                int r = g_rows[(size_t)(t + 1) * MAXA_ + a];
                ((float4*)(cin_sh + (size_t)a * H_))[tid] =
                    ((const float4*)(g_cbuf + (size_t)r * H_))[tid];
            }
        }
        __syncthreads();

        // h16 from shared (broadcast across warps)
        float h16[16];
        {
            const float4* h4 = (const float4*)h_sh;
#pragma unroll
            for (int i = 0; i < 4; i++) {
                float4 v = h4[lane + 32 * i];
                h16[4*i+0] = v.x; h16[4*i+1] = v.y;
                h16[4*i+2] = v.z; h16[4*i+3] = v.w;
            }
        }

        // one FMA pass: 6 dots over h + safe alpha dots over cin
        float d0 = 0.f, d1 = 0.f, d2 = 0.f, di = 0.f, dq = 0.f, dg = 0.f;
#pragma unroll
        for (int i = 0; i < 16; i++) {
            d0 = fmaf(h16[i], wF[i],  d0);
            d1 = fmaf(h16[i], wIw[i], d1);
            d2 = fmaf(h16[i], wGw[i], d2);
            di = fmaf(h16[i], wI[i],  di);
            dq = fmaf(h16[i], wO[i],  dq);
            dg = fmaf(h16[i], wG[i],  dg);
        }
        const int nb = ns < 8 ? ns : 8;
        float dd[8];
#pragma unroll
        for (int a = 0; a < 8; a++) dd[a] = 0.f;
        for (int a = 0; a < nb; a++) {
            const float4* c4 = (const float4*)(cin_sh + (size_t)a * H_);
            float s0 = 0.f, s1 = 0.f, s2 = 0.f, s3 = 0.f;
#pragma unroll
            for (int i = 0; i < 4; i++) {
                float4 cv = c4[lane + 32 * i];
                s0 = fmaf(cv.x, wA[4*i+0], s0);
                s1 = fmaf(cv.y, wA[4*i+1], s1);
                s2 = fmaf(cv.z, wA[4*i+2], s2);
                s3 = fmaf(cv.w, wA[4*i+3], s3);
            }
            dd[a] = (s0 + s1) + (s2 + s3);
        }

        const float c_prev = cx;           // c1(t): seed for word cells of t

        if (need2) {
            // ---------- slow path: word dots reduce FIRST, publish, then the rest ----------
#pragma unroll
            for (int o = 16; o; o >>= 1) {
                d0 += __shfl_xor_sync(0xffffffffu, d0, o);
                d1 += __shfl_xor_sync(0xffffffffu, d1, o);
                d2 += __shfl_xor_sync(0xffffffffu, d2, o);
            }
            if (lane < KW_) {
                float f  = fsig(wwf + d0);
                float iw = fsig(wwq + d1);
                float tg = ftanh(wwg + d2);
                g_cbuf[((size_t)t * KW_ + lane) * H_ + j] = fmaf(f, c_prev, iw * tg);
            }
            bar_arrive_cta(&g_bar[2 * t + 1]);            // c_buf row t published EARLY

            // gate + safe-alpha reduce in the bar2 shadow
#pragma unroll
            for (int o = 16; o; o >>= 1) {
                di += __shfl_xor_sync(0xffffffffu, di, o);
                dq += __shfl_xor_sync(0xffffffffu, dq, o);
                dg += __shfl_xor_sync(0xffffffffu, dg, o);
                for (int a = 0; a < nb; a++)
                    dd[a] += __shfl_xor_sync(0xffffffffu, dd[a], o);
            }
            float gi = fsig(di + wi_t);
            float go = fsig(dq + wo_t);
            float gg = ftanh(dg + wg_t);
            float w_i = fexp(gi);
            float num = w_i * gg, den = w_i;
            for (int a = 0; a < nb; a++) {
                float wa = fexp(fsig(awi_t + dd[a]));
                den += wa;
                num = fmaf(wa, cin_sh[(size_t)a * H_ + j], num);
            }
            for (int a = 8; a < ns; a++) {                // rare: >8 safe rows
                const float4* c4 = (const float4*)(cin_sh + (size_t)a * H_);
                float s = 0.f;
#pragma unroll
                for (int i = 0; i < 4; i++) {
                    float4 cv = c4[lane + 32 * i];
                    s = fmaf(cv.x, wA[4*i+0], s); s = fmaf(cv.y, wA[4*i+1], s);
                    s = fmaf(cv.z, wA[4*i+2], s); s = fmaf(cv.w, wA[4*i+3], s);
                }
#pragma unroll
                for (int o = 16; o; o >>= 1) s += __shfl_xor_sync(0xffffffffu, s, o);
                float wa = fexp(fsig(awi_t + s));
                den += wa; num = fmaf(wa, cin_sh[(size_t)a * H_ + j], num);
            }

            bar_wait_warp(&g_bar[2 * t + 1], GBLK);
            for (int a = ns; a < nact; a++) {
                int r = g_rows[(size_t)(t + 1) * MAXA_ + a];
                ((float4*)(cin_sh + (size_t)a * H_))[tid] =
                    ((const float4*)(g_cbuf + (size_t)r * H_))[tid];
            }
            __syncthreads();
            for (int a = ns; a < nact; a++) {
                const float4* c4 = (const float4*)(cin_sh + (size_t)a * H_);
                float s0 = 0.f, s1 = 0.f, s2 = 0.f, s3 = 0.f;
#pragma unroll
                for (int i = 0; i < 4; i++) {
                    float4 cv = c4[lane + 32 * i];
                    s0 = fmaf(cv.x, wA[4*i+0], s0); s1 = fmaf(cv.y, wA[4*i+1], s1);
                    s2 = fmaf(cv.z, wA[4*i+2], s2); s3 = fmaf(cv.w, wA[4*i+3], s3);
                }
                float s = (s0 + s1) + (s2 + s3);
#pragma unroll
                for (int o = 16; o; o >>= 1) s += __shfl_xor_sync(0xffffffffu, s, o);
                float wa = fexp(fsig(awi_t + s));
                den += wa; num = fmaf(wa, cin_sh[(size_t)a * H_ + j], num);
            }

            float c1 = __fdividef(num, den);              // nact > 0 here
            cx = c1;
            h1 = go * ftanh(c1);
            if (lane == 0)
                out_h[(size_t)(t + 1) * H_ + j] = h1;
            bar1_arrive_warp(&g_bar[2 * (t + 1)], lane);  // per-warp release
        } else {
            // ---------- fast path (~80%): h-critical work only before bar1 ----------
#pragma unroll
            for (int o = 16; o; o >>= 1) {
                di += __shfl_xor_sync(0xffffffffu, di, o);
                dq += __shfl_xor_sync(0xffffffffu, dq, o);
                dg += __shfl_xor_sync(0xffffffffu, dg, o);
                for (int a = 0; a < nb; a++)
                    dd[a] += __shfl_xor_sync(0xffffffffu, dd[a], o);
            }
            float gi = fsig(di + wi_t);
            float go = fsig(dq + wo_t);
            float gg = ftanh(dg + wg_t);
            float c1;
            if (nact > 0) {
                float w_i = fexp(gi);
                float num = w_i * gg, den = w_i;
                for (int a = 0; a < nb; a++) {
                    float wa = fexp(fsig(awi_t + dd[a]));
                    den += wa;
                    num = fmaf(wa, cin_sh[(size_t)a * H_ + j], num);
                }
                for (int a = 8; a < ns; a++) {            // rare: >8 safe rows
                    const float4* c4 = (const float4*)(cin_sh + (size_t)a * H_);
                    float s = 0.f;
#pragma unroll
                    for (int i = 0; i < 4; i++) {
                        float4 cv = c4[lane + 32 * i];
                        s = fmaf(cv.x, wA[4*i+0], s); s = fmaf(cv.y, wA[4*i+1], s);
                        s = fmaf(cv.z, wA[4*i+2], s); s = fmaf(cv.w, wA[4*i+3], s);
                    }
#pragma unroll
                    for (int o = 16; o; o >>= 1) s += __shfl_xor_sync(0xffffffffu, s, o);
                    float wa = fexp(fsig(awi_t + s));
                    den += wa; num = fmaf(wa, cin_sh[(size_t)a * H_ + j], num);
                }
                c1 = __fdividef(num, den);
            } else {
                c1 = fmaf(gi, gg, (1.f - gi) * c_prev);
            }
            cx = c1;
            h1 = go * ftanh(c1);
            if (lane == 0)
                out_h[(size_t)(t + 1) * H_ + j] = h1;
            bar1_arrive_warp(&g_bar[2 * (t + 1)], lane);  // per-warp release, EARLY

            // --- shadow: word-dot reduce + word cells(t) (not needed until later) ---
#pragma unroll
            for (int o = 16; o; o >>= 1) {
                d0 += __shfl_xor_sync(0xffffffffu, d0, o);
                d1 += __shfl_xor_sync(0xffffffffu, d1, o);
                d2 += __shfl_xor_sync(0xffffffffu, d2, o);
            }
            if (lane < KW_) {
                float f  = fsig(wwf + d0);
                float iw = fsig(wwq + d1);
                float tg = ftanh(wwg + d2);
                g_cbuf[((size_t)t * KW_ + lane) * H_ + j] = fmaf(f, c_prev, iw * tg);
            }
        }

        // --- shadow (both paths): out_c store + prefetch for next iteration ---
        if (lane == 0)
            out_c[(size_t)(t + 1) * H_ + j] = cx;
        if (lane < KW_) {
            const float* wr = g_WWI + ((size_t)(t + 1) * KW_ + lane) * H3_ + j;
            wwf = wr[0]; wwq = wr[H_]; wwg = wr[2 * H_];
        }
        if (t + 2 < S_) {
            meta_n = g_meta[t + 2];
            wi_t   = g_WI[(size_t)(t + 2) * H3_ + j];
            wo_t   = g_WI[(size_t)(t + 2) * H3_ + H_ + j];
            wg_t   = g_WI[(size_t)(t + 2) * H3_ + 2 * H_ + j];
            awi_t  = g_AWI[(size_t)(t + 2) * H_ + j];
        } else {
            meta_n = 0;
        }
    }
    // word cells at t = S-1 are never gathered; outputs complete.
}

// ---------------- launch ----------------
extern "C" void kernel_launch(void* const* d_in, const int* in_sizes, int n_in,
                              void* d_out, int out_size)
{
    const float* x        = (const float*)d_in[0];
    const float* W_ih     = (const float*)d_in[1];
    const float* W_hh     = (const float*)d_in[2];
    const float* b        = (const float*)d_in[3];
    const float* aW_ih    = (const float*)d_in[4];
    const float* aW_hh    = (const float*)d_in[5];
    const float* ab       = (const float*)d_in[6];
    const float* Ww_ih    = (const float*)d_in[7];
    const float* Ww_hh    = (const float*)d_in[8];
    const float* bw       = (const float*)d_in[9];
    const float* word_emb = (const float*)d_in[10];
    const int*   word_ids = (const int*)d_in[11];
    const int*   gpos     = (const int*)d_in[12];
    const int*   gslot    = (const int*)d_in[13];
    const int*   gmask    = (const int*)d_in[14];

    const int Km = in_sizes[12] / S_;

    float* out_h = (float*)d_out;
    float* out_c = out_h + (size_t)S_ * H_;

    // launch 1: transposes + barrier clear + act-list metadata
    prep_fused<<<dim3(48, 16, 4), dim3(32, 8)>>>(W_hh, aW_hh, Ww_hh,
                                                 gpos, gslot, gmask, Km);
    // launch 2: fused WI + AWI GEMMs
    gemm_fused<<<dim3(H3_ / 128, S_ / 128, 2), 256>>>(x, W_ih, b, aW_ih, ab);
    // launch 3: WWI GEMM
    gemm_wwi<<<dim3(H3_ / 128, (S_ * KW_) / 128), 256>>>(word_emb, Ww_ih, bw, word_ids);

    // launch 4: persistent scan
    size_t shmem = (size_t)(1 + MAXA_) * H_ * sizeof(float);
    scan_kernel<<<GBLK, NT, shmem>>>(out_h, out_c);
}

// round 17
// speedup vs baseline: 1.0782x; 1.0782x over previous
#include <cuda_runtime.h>

// Problem constants (fixed for this problem instance)
#define S_    2048
#define D_    512
#define H_    512
#define H3_   1536
#define KW_   3
#define MAXA_ 16     // max gather rows per step supported in metadata

#define GBLK 128     // persistent CTAs in scan kernel (all co-resident, 1/SM)
#define NW   4       // warps per CTA; GBLK*NW == H_ (one warp per output j)
#define NT   (NW * 32)

// ---------------- device scratch (static: no runtime allocation) ----------------
__device__ float g_WI [S_ * H3_];
__device__ float g_AWI[S_ * H_];
__device__ float g_WWI[(size_t)S_ * KW_ * H3_];
__device__ float g_WhhT [H3_ * D_];
__device__ float g_aWhhT[H_  * H_];
__device__ float g_WwhhT[H3_ * H_];
__device__ float g_cbuf[(size_t)S_ * KW_ * H_];
__device__ unsigned g_bar[2 * S_];
__device__ int g_meta[S_];                 // nact | nsafe<<8 (rows gathered AT step t)
__device__ int g_rows[S_ * MAXA_];         // row index = pos*KW + slot (safe first)

// ---------------- fast transcendentals (ex2.approx-based; ~1e-6 rel err) ----------------
__device__ __forceinline__ float fexp(float x)
{
    float y;
    asm("ex2.approx.ftz.f32 %0, %1;" : "=f"(y) : "f"(x * 1.4426950408889634f));
    return y;
}
__device__ __forceinline__ float fsig(float x)
{
    return __fdividef(1.f, 1.f + fexp(-x));
}
__device__ __forceinline__ float ftanh(float x)
{
    float e = fexp(-2.f * x);
    return fmaf(2.f, __fdividef(1.f, 1.f + e), -1.f);
}

// ---------------- SGEMM body: C[M,N] = A[M,K] @ B[K,N] + bias ----------------
__device__ __forceinline__ void sgemm_body(
    const float* __restrict__ A, const float* __restrict__ B,
    const float* __restrict__ bias, float* __restrict__ C,
    int M, int N, int K, const int* __restrict__ rowIdx,
    int bx, int by, float As[8][128], float Bs[8][128])
{
    const int tid = threadIdx.x;
    const int tr = tid >> 4;
    const int tc = tid & 15;
    const int arow = tid >> 1;
    const int acol = (tid & 1) * 4;
    const int brow = tid >> 5;
    const int bcol = (tid & 31) * 4;

    const float* Abase;
    {
        int gr = by * 128 + arow;
        size_t r = rowIdx ? (size_t)rowIdx[gr] : (size_t)gr;
        Abase = A + r * (size_t)K + acol;
    }
    const float* Bbase = B + (size_t)brow * N + bx * 128 + bcol;

    float acc[8][8];
#pragma unroll
    for (int i = 0; i < 8; i++)
#pragma unroll
        for (int j = 0; j < 8; j++) acc[i][j] = 0.f;

    for (int k0 = 0; k0 < K; k0 += 8) {
        float4 av = *(const float4*)(Abase + k0);
        As[acol + 0][arow] = av.x;
        As[acol + 1][arow] = av.y;
        As[acol + 2][arow] = av.z;
        As[acol + 3][arow] = av.w;
        float4 bv = *(const float4*)(Bbase + (size_t)k0 * N);
        *(float4*)&Bs[brow][bcol] = bv;
        __syncthreads();
#pragma unroll
        for (int kk = 0; kk < 8; kk++) {
            float ar[8], br[8];
            float4 a0 = *(const float4*)&As[kk][tr * 8];
            float4 a1 = *(const float4*)&As[kk][tr * 8 + 4];
            ar[0] = a0.x; ar[1] = a0.y; ar[2] = a0.z; ar[3] = a0.w;
            ar[4] = a1.x; ar[5] = a1.y; ar[6] = a1.z; ar[7] = a1.w;
            float4 b0 = *(const float4*)&Bs[kk][tc * 8];
            float4 b1 = *(const float4*)&Bs[kk][tc * 8 + 4];
            br[0] = b0.x; br[1] = b0.y; br[2] = b0.z; br[3] = b0.w;
            br[4] = b1.x; br[5] = b1.y; br[6] = b1.z; br[7] = b1.w;
#pragma unroll
            for (int i = 0; i < 8; i++)
#pragma unroll
                for (int j = 0; j < 8; j++)
                    acc[i][j] = fmaf(ar[i], br[j], acc[i][j]);
        }
        __syncthreads();
    }

#pragma unroll
    for (int i = 0; i < 8; i++) {
        int row = by * 128 + tr * 8 + i;
#pragma unroll
        for (int j = 0; j < 8; j++) {
            int col = bx * 128 + tc * 8 + j;
            float v = acc[i][j];
            if (bias) v += bias[col];
            C[(size_t)row * N + col] = v;
        }
    }
}

// ---------------- launch 1: transposes + barrier clear + act-list metadata ----------------
__global__ void prep_fused(const float* __restrict__ w_hh,
                           const float* __restrict__ aw_hh,
                           const float* __restrict__ ww_hh,
                           const int* __restrict__ gpos,
                           const int* __restrict__ gslot,
                           const int* __restrict__ gmask, int Km)
{
    if (blockIdx.z < 3) {
        __shared__ float tile[32][33];
        const float* in; float* out; int R, C;
        if (blockIdx.z == 0)      { in = w_hh;  out = g_WhhT;  R = D_; C = H3_; }
        else if (blockIdx.z == 1) { in = aw_hh; out = g_aWhhT; R = H_; C = H_;  }
        else                      { in = ww_hh; out = g_WwhhT; R = H_; C = H3_; }

        int cx = blockIdx.x * 32, ry = blockIdx.y * 32;
        if (cx >= C || ry >= R) return;
        int x = cx + threadIdx.x;
#pragma unroll
        for (int i = 0; i < 32; i += 8) {
            int y = ry + threadIdx.y + i;
            tile[threadIdx.y + i][threadIdx.x] = in[(size_t)y * C + x];
        }
        __syncthreads();
        int x2 = ry + threadIdx.x;
#pragma unroll
        for (int i = 0; i < 32; i += 8) {
            int y2 = cx + threadIdx.y + i;
            out[(size_t)y2 * R + x2] = tile[threadIdx.x][threadIdx.y + i];
        }
        return;
    }

    // z == 3: clear barrier counters + build act-list metadata (one thread per t)
    int flat = blockIdx.y * gridDim.x + blockIdx.x;
    int g = flat * 256 + threadIdx.y * 32 + threadIdx.x;
    if (g < 2 * S_) g_bar[g] = 0;
    if (g < S_) {
        const int t = g;
        const int* gm = gmask + (size_t)t * Km;
        const int* gp = gpos  + (size_t)t * Km;
        const int* gs = gslot + (size_t)t * Km;
        int n = 0;
        for (int k = 0; k < Km && n < MAXA_; k++)      // safe rows first (pos < t-1)
            if (gm[k] && gp[k] != t - 1)
                g_rows[t * MAXA_ + n++] = gp[k] * KW_ + gs[k];
        int nsafe = n;
        for (int k = 0; k < Km && n < MAXA_; k++)      // fresh rows last (pos == t-1)
            if (gm[k] && gp[k] == t - 1)
                g_rows[t * MAXA_ + n++] = gp[k] * KW_ + gs[k];
        g_meta[t] = n | (nsafe << 8);
    }
}

// ---------------- launch 2: fused WI + AWI GEMMs ----------------
__global__ void __launch_bounds__(256) gemm_fused(
    const float* __restrict__ x,
    const float* __restrict__ W_ih, const float* __restrict__ b,
    const float* __restrict__ aW_ih, const float* __restrict__ ab)
{
    __shared__ float As[8][128];
    __shared__ float Bs[8][128];
    const int z = blockIdx.z;
    if (z == 1 && blockIdx.x >= H_ / 128) return;
    const float* B    = z ? aW_ih : W_ih;
    const float* bias = z ? ab    : b;
    float* C          = z ? g_AWI : g_WI;
    int N             = z ? H_    : H3_;
    sgemm_body(x, B, bias, C, S_, N, D_, nullptr, blockIdx.x, blockIdx.y, As, Bs);
}

// ---------------- launch 3: WWI GEMM (embedding-gathered A) ----------------
__global__ void __launch_bounds__(256) gemm_wwi(
    const float* __restrict__ word_emb, const float* __restrict__ Ww_ih,
    const float* __restrict__ bw, const int* __restrict__ word_ids)
{
    __shared__ float As[8][128];
    __shared__ float Bs[8][128];
    sgemm_body(word_emb, Ww_ih, bw, g_WWI, S_ * KW_, H3_, D_, word_ids,
               blockIdx.x, blockIdx.y, As, Bs);
}

// ---------------- scan helpers ----------------
__device__ __forceinline__ void load_row16(const float* base, int lane, float* r)
{
    const float4* p = (const float4*)base;
#pragma unroll
    for (int i = 0; i < 4; i++) {
        float4 v = p[lane + 32 * i];
        r[4 * i + 0] = v.x; r[4 * i + 1] = v.y;
        r[4 * i + 2] = v.z; r[4 * i + 3] = v.w;
    }
}

__device__ __forceinline__ void bar_arrive(unsigned* ctr)
{
    __syncthreads();                 // all CTA work ordered before the release
    if (threadIdx.x == 0)
        asm volatile("red.release.gpu.global.add.u32 [%0], 1;" :: "l"(ctr) : "memory");
}

// warp-independent wait: every warp polls; no CTA-wide resync.
__device__ __forceinline__ void bar_wait_warp(unsigned* ctr)
{
    unsigned v;
    do {
        asm volatile("ld.acquire.gpu.global.u32 %0, [%1];" : "=r"(v) : "l"(ctr) : "memory");
    } while (v < (unsigned)GBLK);
}

// ---------------- persistent sequential scan (h-first merged loop) ----------------
// Fast path (~80%, no fresh rows at t+1): h-critical reduce -> gates -> c1,h1
//   -> STG -> bar1 arrive -> SHADOW: word reduce + word cells(t) + prefetch.
// Slow path (~20%): word-dot reduce FIRST -> word cells -> bar2 arrive ->
//   gate/alpha reduce in bar2 shadow -> safe merge -> bar2 wait -> fresh merge
//   -> c1,h1 -> bar1 arrive.
__global__ void __launch_bounds__(NT, 1) scan_kernel(
    float* __restrict__ out_h, float* __restrict__ out_c)
{
    extern __shared__ float sm[];
    float* h_sh   = sm;            // H_ floats
    float* cin_sh = sm + H_;       // MAXA_ * H_ floats

    const int tid  = threadIdx.x;
    const int lane = tid & 31;
    const int wid  = tid >> 5;
    const int j    = blockIdx.x * NW + wid;              // 0..511

    // register-resident weight rows (columns of the original matrices)
    float wI[16], wO[16], wG[16], wA[16], wF[16], wIw[16], wGw[16];
    load_row16(g_WhhT  + (size_t)(0    + j) * D_, lane, wI);
    load_row16(g_WhhT  + (size_t)(H_   + j) * D_, lane, wO);
    load_row16(g_WhhT  + (size_t)(2*H_ + j) * D_, lane, wG);
    load_row16(g_aWhhT + (size_t)j * H_,          lane, wA);
    load_row16(g_WwhhT + (size_t)(0    + j) * H_, lane, wF);
    load_row16(g_WwhhT + (size_t)(H_   + j) * H_, lane, wIw);
    load_row16(g_WwhhT + (size_t)(2*H_ + j) * H_, lane, wGw);

    // ---- prologue: step 0 (h = 0; no words end at t=0 since len >= 2) ----
    float cx, h1;
    {
        float gi = fsig(g_WI[j]);
        float go = fsig(g_WI[H_ + j]);
        float gg = ftanh(g_WI[2 * H_ + j]);
        cx = gi * gg;                      // (1-i)*0 + i*g
        h1 = go * ftanh(cx);
        if (lane == 0) { out_h[j] = h1; out_c[j] = cx; }
    }
    bar_arrive(&g_bar[0]);

    // shadow: WWI gates for word cells of t=0; meta/scalars for t+1 = 1
    float wwf = 0.f, wwq = 0.f, wwg = 0.f;
    if (lane < KW_) {
        const float* wr = g_WWI + (size_t)lane * H3_ + j;
        wwf = wr[0]; wwq = wr[H_]; wwg = wr[2 * H_];
    }
    int   meta_n = g_meta[1];
    float wi_t  = g_WI[(size_t)H3_ + j];
    float wo_t  = g_WI[(size_t)H3_ + H_ + j];
    float wg_t  = g_WI[(size_t)H3_ + 2 * H_ + j];
    float awi_t = g_AWI[(size_t)H_ + j];

    for (int t = 0; t < S_ - 1; t++) {
        bar_wait_warp(&g_bar[2 * t]);                     // h(t) visible

        const int nact = meta_n & 0xff;
        const int ns   = (meta_n >> 8) & 0xff;
        const bool need2 = nact > ns;                     // grid-uniform

        // coop stage: h(t) row + safe cin rows for t+1
        {
            ((float4*)h_sh)[tid] = ((const float4*)(out_h + (size_t)t * H_))[tid];
            for (int a = 0; a < ns; a++) {
                int r = g_rows[(size_t)(t + 1) * MAXA_ + a];
                ((float4*)(cin_sh + (size_t)a * H_))[tid] =
                    ((const float4*)(g_cbuf + (size_t)r * H_))[tid];
            }
        }
        __syncthreads();

        // h16 from shared (broadcast across warps)
        float h16[16];
        {
            const float4* h4 = (const float4*)h_sh;
#pragma unroll
            for (int i = 0; i < 4; i++) {
                float4 v = h4[lane + 32 * i];
                h16[4*i+0] = v.x; h16[4*i+1] = v.y;
                h16[4*i+2] = v.z; h16[4*i+3] = v.w;
            }
        }

        // one FMA pass: 6 dots over h + safe alpha dots over cin
        float d0 = 0.f, d1 = 0.f, d2 = 0.f, di = 0.f, dq = 0.f, dg = 0.f;
#pragma unroll
        for (int i = 0; i < 16; i++) {
            d0 = fmaf(h16[i], wF[i],  d0);
            d1 = fmaf(h16[i], wIw[i], d1);
            d2 = fmaf(h16[i], wGw[i], d2);
            di = fmaf(h16[i], wI[i],  di);
            dq = fmaf(h16[i], wO[i],  dq);
            dg = fmaf(h16[i], wG[i],  dg);
        }
        const int nb = ns < 8 ? ns : 8;
        float dd[8];
#pragma unroll
        for (int a = 0; a < 8; a++) dd[a] = 0.f;
        for (int a = 0; a < nb; a++) {
            const float4* c4 = (const float4*)(cin_sh + (size_t)a * H_);
            float s0 = 0.f, s1 = 0.f, s2 = 0.f, s3 = 0.f;
#pragma unroll
            for (int i = 0; i < 4; i++) {
                float4 cv = c4[lane + 32 * i];
                s0 = fmaf(cv.x, wA[4*i+0], s0);
                s1 = fmaf(cv.y, wA[4*i+1], s1);
                s2 = fmaf(cv.z, wA[4*i+2], s2);
                s3 = fmaf(cv.w, wA[4*i+3], s3);
            }
            dd[a] = (s0 + s1) + (s2 + s3);
        }

        const float c_prev = cx;           // c1(t): seed for word cells of t

        if (need2) {
            // ---------- slow path: word dots reduce FIRST, publish early ----------
#pragma unroll
            for (int o = 16; o; o >>= 1) {
                d0 += __shfl_xor_sync(0xffffffffu, d0, o);
                d1 += __shfl_xor_sync(0xffffffffu, d1, o);
                d2 += __shfl_xor_sync(0xffffffffu, d2, o);
            }
            if (lane < KW_) {
                float f  = fsig(wwf + d0);
                float iw = fsig(wwq + d1);
                float tg = ftanh(wwg + d2);
                g_cbuf[((size_t)t * KW_ + lane) * H_ + j] = fmaf(f, c_prev, iw * tg);
            }
            bar_arrive(&g_bar[2 * t + 1]);                // c_buf row t published EARLY

            // gate + safe-alpha reduce in the bar2 shadow
#pragma unroll
            for (int o = 16; o; o >>= 1) {
                di += __shfl_xor_sync(0xffffffffu, di, o);
                dq += __shfl_xor_sync(0xffffffffu, dq, o);
                dg += __shfl_xor_sync(0xffffffffu, dg, o);
                for (int a = 0; a < nb; a++)
                    dd[a] += __shfl_xor_sync(0xffffffffu, dd[a], o);
            }
            float gi = fsig(di + wi_t);
            float go = fsig(dq + wo_t);
            float gg = ftanh(dg + wg_t);
            float w_i = fexp(gi);
            float num = w_i * gg, den = w_i;
            for (int a = 0; a < nb; a++) {
                float wa = fexp(fsig(awi_t + dd[a]));
                den += wa;
                num = fmaf(wa, cin_sh[(size_t)a * H_ + j], num);
            }
            for (int a = 8; a < ns; a++) {                // rare: >8 safe rows
                const float4* c4 = (const float4*)(cin_sh + (size_t)a * H_);
                float s = 0.f;
#pragma unroll
                for (int i = 0; i < 4; i++) {
                    float4 cv = c4[lane + 32 * i];
                    s = fmaf(cv.x, wA[4*i+0], s); s = fmaf(cv.y, wA[4*i+1], s);
                    s = fmaf(cv.z, wA[4*i+2], s); s = fmaf(cv.w, wA[4*i+3], s);
                }
#pragma unroll
                for (int o = 16; o; o >>= 1) s += __shfl_xor_sync(0xffffffffu, s, o);
                float wa = fexp(fsig(awi_t + s));
                den += wa; num = fmaf(wa, cin_sh[(size_t)a * H_ + j], num);
            }

            bar_wait_warp(&g_bar[2 * t + 1]);
            for (int a = ns; a < nact; a++) {
                int r = g_rows[(size_t)(t + 1) * MAXA_ + a];
                ((float4*)(cin_sh + (size_t)a * H_))[tid] =
                    ((const float4*)(g_cbuf + (size_t)r * H_))[tid];
            }
            __syncthreads();
            for (int a = ns; a < nact; a++) {
                const float4* c4 = (const float4*)(cin_sh + (size_t)a * H_);
                float s0 = 0.f, s1 = 0.f, s2 = 0.f, s3 = 0.f;
#pragma unroll
                for (int i = 0; i < 4; i++) {
                    float4 cv = c4[lane + 32 * i];
                    s0 = fmaf(cv.x, wA[4*i+0], s0); s1 = fmaf(cv.y, wA[4*i+1], s1);
                    s2 = fmaf(cv.z, wA[4*i+2], s2); s3 = fmaf(cv.w, wA[4*i+3], s3);
                }
                float s = (s0 + s1) + (s2 + s3);
#pragma unroll
                for (int o = 16; o; o >>= 1) s += __shfl_xor_sync(0xffffffffu, s, o);
                float wa = fexp(fsig(awi_t + s));
                den += wa; num = fmaf(wa, cin_sh[(size_t)a * H_ + j], num);
            }

            float c1 = __fdividef(num, den);              // nact > 0 here
            cx = c1;
            h1 = go * ftanh(c1);
            if (lane == 0)
                out_h[(size_t)(t + 1) * H_ + j] = h1;
            bar_arrive(&g_bar[2 * (t + 1)]);              // h1(t+1) published
        } else {
            // ---------- fast path (~80%): h-critical work only before bar1 ----------
#pragma unroll
            for (int o = 16; o; o >>= 1) {
                di += __shfl_xor_sync(0xffffffffu, di, o);
                dq += __shfl_xor_sync(0xffffffffu, dq, o);
                dg += __shfl_xor_sync(0xffffffffu, dg, o);
                for (int a = 0; a < nb; a++)
                    dd[a] += __shfl_xor_sync(0xffffffffu, dd[a], o);
            }
            float gi = fsig(di + wi_t);
            float go = fsig(dq + wo_t);
            float gg = ftanh(dg + wg_t);
            float c1;
            if (nact > 0) {
                float w_i = fexp(gi);
                float num = w_i * gg, den = w_i;
                for (int a = 0; a < nb; a++) {
                    float wa = fexp(fsig(awi_t + dd[a]));
                    den += wa;
                    num = fmaf(wa, cin_sh[(size_t)a * H_ + j], num);
                }
                for (int a = 8; a < ns; a++) {            // rare: >8 safe rows
                    const float4* c4 = (const float4*)(cin_sh + (size_t)a * H_);
                    float s = 0.f;
#pragma unroll
                    for (int i = 0; i < 4; i++) {
                        float4 cv = c4[lane + 32 * i];
                        s = fmaf(cv.x, wA[4*i+0], s); s = fmaf(cv.y, wA[4*i+1], s);
                        s = fmaf(cv.z, wA[4*i+2], s); s = fmaf(cv.w, wA[4*i+3], s);
                    }
#pragma unroll
                    for (int o = 16; o; o >>= 1) s += __shfl_xor_sync(0xffffffffu, s, o);
                    float wa = fexp(fsig(awi_t + s));
                    den += wa; num = fmaf(wa, cin_sh[(size_t)a * H_ + j], num);
                }
                c1 = __fdividef(num, den);
            } else {
                c1 = fmaf(gi, gg, (1.f - gi) * c_prev);
            }
            cx = c1;
            h1 = go * ftanh(c1);
            if (lane == 0)
                out_h[(size_t)(t + 1) * H_ + j] = h1;
            bar_arrive(&g_bar[2 * (t + 1)]);              // h1(t+1) published EARLY

            // --- shadow: word-dot reduce + word cells(t) (not needed until later) ---
#pragma unroll
            for (int o = 16; o; o >>= 1) {
                d0 += __shfl_xor_sync(0xffffffffu, d0, o);
                d1 += __shfl_xor_sync(0xffffffffu, d1, o);
                d2 += __shfl_xor_sync(0xffffffffu, d2, o);
            }
            if (lane < KW_) {
                float f  = fsig(wwf + d0);
                float iw = fsig(wwq + d1);
                float tg = ftanh(wwg + d2);
                g_cbuf[((size_t)t * KW_ + lane) * H_ + j] = fmaf(f, c_prev, iw * tg);
            }
        }

        // --- shadow (both paths): out_c store + prefetch for next iteration ---
        if (lane == 0)
            out_c[(size_t)(t + 1) * H_ + j] = cx;
        if (lane < KW_) {
            const float* wr = g_WWI + ((size_t)(t + 1) * KW_ + lane) * H3_ + j;
            wwf = wr[0]; wwq = wr[H_]; wwg = wr[2 * H_];
        }
        if (t + 2 < S_) {
            meta_n = g_meta[t + 2];
            wi_t   = g_WI[(size_t)(t + 2) * H3_ + j];
            wo_t   = g_WI[(size_t)(t + 2) * H3_ + H_ + j];
            wg_t   = g_WI[(size_t)(t + 2) * H3_ + 2 * H_ + j];
            awi_t  = g_AWI[(size_t)(t + 2) * H_ + j];
        } else {
            meta_n = 0;
        }
    }
    // word cells at t = S-1 are never gathered; outputs complete.
}

// ---------------- launch ----------------
extern "C" void kernel_launch(void* const* d_in, const int* in_sizes, int n_in,
                              void* d_out, int out_size)
{
    const float* x        = (const float*)d_in[0];
    const float* W_ih     = (const float*)d_in[1];
    const float* W_hh     = (const float*)d_in[2];
    const float* b        = (const float*)d_in[3];
    const float* aW_ih    = (const float*)d_in[4];
    const float* aW_hh    = (const float*)d_in[5];
    const float* ab       = (const float*)d_in[6];
    const float* Ww_ih    = (const float*)d_in[7];
    const float* Ww_hh    = (const float*)d_in[8];
    const float* bw       = (const float*)d_in[9];
    const float* word_emb = (const float*)d_in[10];
    const int*   word_ids = (const int*)d_in[11];
    const int*   gpos     = (const int*)d_in[12];
    const int*   gslot    = (const int*)d_in[13];
    const int*   gmask    = (const int*)d_in[14];

    const int Km = in_sizes[12] / S_;

    float* out_h = (float*)d_out;
    float* out_c = out_h + (size_t)S_ * H_;

    // launch 1: transposes + barrier clear + act-list metadata
    prep_fused<<<dim3(48, 16, 4), dim3(32, 8)>>>(W_hh, aW_hh, Ww_hh,
                                                 gpos, gslot, gmask, Km);
    // launch 2: fused WI + AWI GEMMs
    gemm_fused<<<dim3(H3_ / 128, S_ / 128, 2), 256>>>(x, W_ih, b, aW_ih, ab);
    // launch 3: WWI GEMM
    gemm_wwi<<<dim3(H3_ / 128, (S_ * KW_) / 128), 256>>>(word_emb, Ww_ih, bw, word_ids);

    // launch 4: persistent scan
    size_t shmem = (size_t)(1 + MAXA_) * H_ * sizeof(float);
    scan_kernel<<<GBLK, NT, shmem>>>(out_h, out_c);
}